// round 8
// baseline (speedup 1.0000x reference)
#include <cuda_runtime.h>
#include <cuda_bf16.h>
#include <math.h>
#include <stdint.h>

#define NN 65536
#define KK 1024
#define DD 256
#define MARGIN 0.1f
#define VTOL   0.2f

#define RPAD  80                 // bytes per smem row: 32 bf16 (64B) + 16 pad
#define ABYTES (128 * RPAD)      // one 128x32-bf16 array: 10240 B
#define SM_RED (8 * ABYTES)      // 81920: reduction scratch
#define SM_TOTAL (SM_RED + 12288)

// ---------------- device scratch (static: no allocation allowed) ----------
__device__ __align__(256) __nv_bfloat16 g_xhi[(size_t)NN * DD];
__device__ __align__(256) __nv_bfloat16 g_xlo[(size_t)NN * DD];
__device__ __align__(256) __nv_bfloat16 g_chi[(size_t)KK * DD];
__device__ __align__(256) __nv_bfloat16 g_clo[(size_t)KK * DD];
__device__ float g_csq[KK];
__device__ int   g_idx[NN];
__device__ float g_bv[NN];
__device__ int   g_tilebad[NN / 128];
__device__ float g_counts[KK];
__device__ float g_sse;
__device__ int   g_nflag;
__device__ int   g_flag[NN];

// ---------------- helpers ---------------------------------------------------
__device__ __forceinline__ uint32_t smem_u32(const void* p) {
    uint32_t a;
    asm("{ .reg .u64 t; cvta.to.shared.u64 t, %1; cvt.u32.u64 %0, t; }" : "=r"(a) : "l"(p));
    return a;
}
__device__ __forceinline__ void cpasync16(uint32_t dst, const void* src) {
    asm volatile("cp.async.cg.shared.global [%0], [%1], 16;" :: "r"(dst), "l"(src) : "memory");
}
__device__ __forceinline__ void ldsm4(uint32_t* r, uint32_t addr) {
    asm volatile("ldmatrix.sync.aligned.m8n8.x4.shared.b16 {%0,%1,%2,%3}, [%4];"
                 : "=r"(r[0]), "=r"(r[1]), "=r"(r[2]), "=r"(r[3]) : "r"(addr));
}
__device__ __forceinline__ void ldsm2(uint32_t& r0, uint32_t& r1, uint32_t addr) {
    asm volatile("ldmatrix.sync.aligned.m8n8.x2.shared.b16 {%0,%1}, [%2];"
                 : "=r"(r0), "=r"(r1) : "r"(addr));
}
__device__ __forceinline__ void mma16816(float* c, const uint32_t* a, uint32_t b0, uint32_t b1) {
    asm volatile(
        "mma.sync.aligned.m16n8k16.row.col.f32.bf16.bf16.f32 "
        "{%0,%1,%2,%3}, {%4,%5,%6,%7}, {%8,%9}, {%0,%1,%2,%3};"
        : "+f"(c[0]), "+f"(c[1]), "+f"(c[2]), "+f"(c[3])
        : "r"(a[0]), "r"(a[1]), "r"(a[2]), "r"(a[3]), "r"(b0), "r"(b1));
}
// packed f32x2 helpers for the exact fallback GEMM
__device__ __forceinline__ unsigned long long pk2(float lo, float hi) {
    unsigned long long r;
    asm("mov.b64 %0, {%1, %2};" : "=l"(r) : "f"(lo), "f"(hi));
    return r;
}
__device__ __forceinline__ void unpk2(unsigned long long v, float& lo, float& hi) {
    asm("mov.b64 {%0, %1}, %2;" : "=f"(lo), "=f"(hi) : "l"(v));
}
__device__ __forceinline__ void fma2(unsigned long long& acc,
                                     unsigned long long a, unsigned long long b) {
    asm("fma.rn.f32x2 %0, %1, %2, %0;" : "+l"(acc) : "l"(a), "l"(b));
}

// ---------------- setup kernels --------------------------------------------
__global__ void init_kernel() {
    int t = blockIdx.x * blockDim.x + threadIdx.x;
    if (t < KK) g_counts[t] = 0.f;
    if (t < NN / 128) g_tilebad[t] = 0;
    if (t == 0) { g_sse = 0.f; g_nflag = 0; }
}

__global__ void convert_kernel(const float* __restrict__ src,
                               __nv_bfloat16* __restrict__ hi,
                               __nv_bfloat16* __restrict__ lo, int ngroups) {
    for (int i = blockIdx.x * blockDim.x + threadIdx.x; i < ngroups; i += gridDim.x * blockDim.x) {
        float4 v = ((const float4*)src)[i];
        __nv_bfloat16 h0 = __float2bfloat16(v.x), h1 = __float2bfloat16(v.y);
        __nv_bfloat16 h2 = __float2bfloat16(v.z), h3 = __float2bfloat16(v.w);
        __nv_bfloat16 l0 = __float2bfloat16(v.x - __bfloat162float(h0));
        __nv_bfloat16 l1 = __float2bfloat16(v.y - __bfloat162float(h1));
        __nv_bfloat16 l2 = __float2bfloat16(v.z - __bfloat162float(h2));
        __nv_bfloat16 l3 = __float2bfloat16(v.w - __bfloat162float(h3));
        __nv_bfloat162* H = (__nv_bfloat162*)hi;
        __nv_bfloat162* L = (__nv_bfloat162*)lo;
        H[i * 2]     = __nv_bfloat162(h0, h1);
        H[i * 2 + 1] = __nv_bfloat162(h2, h3);
        L[i * 2]     = __nv_bfloat162(l0, l1);
        L[i * 2 + 1] = __nv_bfloat162(l2, l3);
    }
}

__global__ void csq_kernel(const float* __restrict__ cb) {
    int warp = (blockIdx.x * blockDim.x + threadIdx.x) >> 5;
    int lane = threadIdx.x & 31;
    if (warp >= KK) return;
    const float* c = cb + (size_t)warp * DD;
    float s = 0.f;
    #pragma unroll
    for (int d = lane; d < DD; d += 32) { float v = c[d]; s += v * v; }
    #pragma unroll
    for (int o = 16; o; o >>= 1) s += __shfl_down_sync(0xffffffffu, s, o);
    if (lane == 0) g_csq[warp] = s;
}

// ---------------- mma.sync argmin kernel (validated downstream) -------------
__device__ __forceinline__ void load_chunk(uint32_t sb, int parity, int ct, int dc,
                                           int row_base, int tid) {
    const uint32_t base = sb + (uint32_t)parity * 4 * ABYTES;
    #pragma unroll
    for (int arr = 0; arr < 4; ++arr) {
        const __nv_bfloat16* src =
            (arr == 0) ? g_xhi + (size_t)row_base * DD :
            (arr == 1) ? g_xlo + (size_t)row_base * DD :
            (arr == 2) ? g_chi + (size_t)ct * 128 * DD :
                         g_clo + (size_t)ct * 128 * DD;
        #pragma unroll
        for (int s = 0; s < 2; ++s) {
            int gl = tid + s * 256;
            int r = gl >> 2, q = gl & 3;
            cpasync16(base + arr * ABYTES + r * RPAD + q * 16,
                      src + (size_t)r * DD + dc * 32 + q * 8);
        }
    }
    asm volatile("cp.async.commit_group;" ::: "memory");
}

__global__ void __launch_bounds__(256) argmin_mma_kernel(float* __restrict__ out_idx_f) {
    extern __shared__ char smem[];
    const uint32_t sb = smem_u32(smem);
    const int tid = threadIdx.x;
    const int lane = tid & 31;
    const int wid = tid >> 5;
    const int wy = wid & 3;
    const int wx = wid >> 2;
    const int gid = lane >> 2;
    const int tig = lane & 3;
    const int row_base = blockIdx.x * 128;

    float acc[2][8][4];
    #pragma unroll
    for (int mt = 0; mt < 2; ++mt)
        #pragma unroll
        for (int j = 0; j < 8; ++j)
            #pragma unroll
            for (int c = 0; c < 4; ++c) acc[mt][j][c] = 0.f;

    float tb1[4], tb2[4];
    int   ti1[4];
    #pragma unroll
    for (int h = 0; h < 4; ++h) { tb1[h] = 3.4e38f; tb2[h] = 3.4e38f; ti1[h] = 0; }

    const uint32_t a_row_off = (uint32_t)((lane & 7) + ((lane >> 3) & 1) * 8) * RPAD
                             + (uint32_t)(lane >> 4) * 16;
    const uint32_t b_row_off = (uint32_t)(lane & 7) * RPAD
                             + (uint32_t)((lane >> 3) & 1) * 16;

    load_chunk(sb, 0, 0, 0, row_base, tid);

    for (int it = 0; it < 64; ++it) {
        const int ct = it >> 3;
        if (it < 63) {
            const int nx = it + 1;
            load_chunk(sb, nx & 1, nx >> 3, nx & 7, row_base, tid);
            asm volatile("cp.async.wait_group 1;" ::: "memory");
        } else {
            asm volatile("cp.async.wait_group 0;" ::: "memory");
        }
        __syncthreads();

        const uint32_t bufs = sb + (uint32_t)(it & 1) * 4 * ABYTES;
        const uint32_t sAhi = bufs;
        const uint32_t sAlo = bufs + ABYTES;
        const uint32_t sBhi = bufs + 2 * ABYTES;
        const uint32_t sBlo = bufs + 3 * ABYTES;

        #pragma unroll
        for (int ks = 0; ks < 2; ++ks) {
            uint32_t ahi[2][4], alo[2][4];
            #pragma unroll
            for (int mt = 0; mt < 2; ++mt) {
                const uint32_t ra = (uint32_t)(wy * 32 + mt * 16) * RPAD + a_row_off + ks * 32;
                ldsm4(ahi[mt], sAhi + ra);
                ldsm4(alo[mt], sAlo + ra);
            }
            #pragma unroll
            for (int j = 0; j < 8; ++j) {
                const uint32_t rb = (uint32_t)(wx * 64 + j * 8) * RPAD + b_row_off + ks * 32;
                uint32_t bh0, bh1, bl0, bl1;
                ldsm2(bh0, bh1, sBhi + rb);
                ldsm2(bl0, bl1, sBlo + rb);
                #pragma unroll
                for (int mt = 0; mt < 2; ++mt) {
                    mma16816(acc[mt][j], ahi[mt], bh0, bh1);
                    mma16816(acc[mt][j], alo[mt], bh0, bh1);
                    mma16816(acc[mt][j], ahi[mt], bl0, bl1);
                }
            }
        }
        __syncthreads();

        if ((it & 7) == 7) {
            #pragma unroll
            for (int j = 0; j < 8; ++j) {
                #pragma unroll
                for (int c = 0; c < 2; ++c) {
                    const int col = ct * 128 + wx * 64 + j * 8 + 2 * tig + c;
                    const float cq = g_csq[col];
                    #pragma unroll
                    for (int mt = 0; mt < 2; ++mt) {
                        #pragma unroll
                        for (int ro = 0; ro < 2; ++ro) {
                            const int h = mt * 2 + ro;
                            float v = fmaf(-2.f, acc[mt][j][ro * 2 + c], cq);
                            if (v < tb1[h])      { tb2[h] = tb1[h]; tb1[h] = v; ti1[h] = col; }
                            else if (v < tb2[h]) { tb2[h] = v; }
                            acc[mt][j][ro * 2 + c] = 0.f;
                        }
                    }
                }
            }
        }
    }

    float* s_v1 = (float*)(smem + SM_RED);
    float* s_v2 = (float*)(smem + SM_RED + 4096);
    int*   s_i1 = (int*)  (smem + SM_RED + 8192);
    #pragma unroll
    for (int h = 0; h < 4; ++h) {
        const int mt = h >> 1, ro = h & 1;
        const int row_local = wy * 32 + mt * 16 + gid + ro * 8;
        const int slot = row_local * 8 + wx * 4 + tig;
        s_v1[slot] = tb1[h]; s_v2[slot] = tb2[h]; s_i1[slot] = ti1[h];
    }
    __syncthreads();
    if (tid < 128) {
        float b1 = 3.4e38f, b2 = 3.4e38f;
        int   i1 = 0;
        #pragma unroll
        for (int s = 0; s < 8; ++s) {
            float v1 = s_v1[tid * 8 + s];
            float v2 = s_v2[tid * 8 + s];
            int   ix = s_i1[tid * 8 + s];
            if (v1 < b1 || (v1 == b1 && ix < i1)) { b2 = fminf(b1, v2); b1 = v1; i1 = ix; }
            else { b2 = fminf(b2, v1); }
        }
        const int row = row_base + tid;
        g_idx[row] = i1;
        g_bv[row] = b1;
        out_idx_f[row] = (float)i1;
        if (b2 - b1 < MARGIN) {
            int s = atomicAdd(&g_nflag, 1);
            g_flag[s] = row;
        }
    }
}

// ---------------- validation: exact score of chosen index vs claimed -------
__global__ void validate_kernel(const float* __restrict__ x,
                                const float* __restrict__ cb) {
    const int r = threadIdx.x >> 1;
    const int h = threadIdx.x & 1;
    const int row = blockIdx.x * 128 + r;
    const int idx = g_idx[row];
    const float4* xp = (const float4*)(x + (size_t)row * DD) + h * 32;
    const float4* cp = (const float4*)(cb + (size_t)idx * DD) + h * 32;
    float dot = 0.f;
    #pragma unroll
    for (int i = 0; i < 32; ++i) {
        float4 a = xp[i], b = cp[i];
        dot += a.x * b.x + a.y * b.y + a.z * b.z + a.w * b.w;
    }
    dot += __shfl_xor_sync(0xffffffffu, dot, 1);
    if (h == 0) {
        float s = g_csq[idx] - 2.f * dot;
        if (fabsf(s - g_bv[row]) > VTOL) g_tilebad[blockIdx.x] = 1;
    }
}

// ---------------- exact fp32 fallback (proven 933us kernel, tile-gated) ----
__global__ void __launch_bounds__(256) argmin_exact_kernel(
    const float* __restrict__ x,
    const float* __restrict__ cb,
    float* __restrict__ out_idx_f)
{
    if (!g_tilebad[blockIdx.x]) return;
    __shared__ float As[8][132];
    __shared__ float Bs[8][132];
    __shared__ float s_val[128 * 16];
    __shared__ int   s_idx[128 * 16];

    const int tid = threadIdx.x;
    const int tx = tid & 15;
    const int ty = tid >> 4;
    const int row_base = blockIdx.x * 128;
    const int lr = tid >> 1;
    const int lc = (tid & 1) * 4;

    float best_val[8];
    int   best_idx[8];
    #pragma unroll
    for (int i = 0; i < 8; ++i) { best_val[i] = 3.4e38f; best_idx[i] = 0; }

    for (int kt = 0; kt < KK / 128; ++kt) {
        unsigned long long acc2[4][8];
        #pragma unroll
        for (int i = 0; i < 4; ++i)
            #pragma unroll
            for (int j = 0; j < 8; ++j) acc2[i][j] = 0ULL;

        for (int dc = 0; dc < DD / 8; ++dc) {
            const int d0 = dc * 8;
            float4 av = *(const float4*)(x  + (size_t)(row_base + lr)  * DD + d0 + lc);
            float4 bv = *(const float4*)(cb + (size_t)(kt * 128 + lr) * DD + d0 + lc);
            __syncthreads();
            As[lc + 0][lr] = av.x; As[lc + 1][lr] = av.y;
            As[lc + 2][lr] = av.z; As[lc + 3][lr] = av.w;
            Bs[lc + 0][lr] = bv.x; Bs[lc + 1][lr] = bv.y;
            Bs[lc + 2][lr] = bv.z; Bs[lc + 3][lr] = bv.w;
            __syncthreads();

            #pragma unroll
            for (int kk = 0; kk < 8; ++kk) {
                float4 a0 = *(const float4*)&As[kk][ty * 8];
                float4 a1 = *(const float4*)&As[kk][ty * 8 + 4];
                float4 b0 = *(const float4*)&Bs[kk][tx * 8];
                float4 b1 = *(const float4*)&Bs[kk][tx * 8 + 4];
                unsigned long long ap[4];
                ap[0] = pk2(a0.x, a0.y); ap[1] = pk2(a0.z, a0.w);
                ap[2] = pk2(a1.x, a1.y); ap[3] = pk2(a1.z, a1.w);
                float bf[8] = {b0.x, b0.y, b0.z, b0.w, b1.x, b1.y, b1.z, b1.w};
                #pragma unroll
                for (int j = 0; j < 8; ++j) {
                    unsigned long long bj = pk2(bf[j], bf[j]);
                    #pragma unroll
                    for (int i = 0; i < 4; ++i) fma2(acc2[i][j], ap[i], bj);
                }
            }
        }

        const int colb = kt * 128 + tx * 8;
        #pragma unroll
        for (int j = 0; j < 8; ++j) {
            const float cq = g_csq[colb + j];
            const int col = colb + j;
            #pragma unroll
            for (int i = 0; i < 4; ++i) {
                float lo, hi;
                unpk2(acc2[i][j], lo, hi);
                float v0 = cq - 2.f * lo;
                float v1 = cq - 2.f * hi;
                if (v0 < best_val[2 * i])     { best_val[2 * i]     = v0; best_idx[2 * i]     = col; }
                if (v1 < best_val[2 * i + 1]) { best_val[2 * i + 1] = v1; best_idx[2 * i + 1] = col; }
            }
        }
    }

    #pragma unroll
    for (int i = 0; i < 8; ++i) {
        s_val[(ty * 8 + i) * 16 + tx] = best_val[i];
        s_idx[(ty * 8 + i) * 16 + tx] = best_idx[i];
    }
    __syncthreads();
    if (tid < 128) {
        float bv = s_val[tid * 16];
        int   bi = s_idx[tid * 16];
        #pragma unroll
        for (int t = 1; t < 16; ++t) {
            float v  = s_val[tid * 16 + t];
            int   ix = s_idx[tid * 16 + t];
            if (v < bv || (v == bv && ix < bi)) { bv = v; bi = ix; }
        }
        g_idx[row_base + tid] = bi;
        out_idx_f[row_base + tid] = (float)bi;
    }
}

// ---------------- exact fp32 rescan of near-tie rows ------------------------
__global__ void rescan_kernel(const float* __restrict__ x,
                              const float* __restrict__ cb,
                              float* __restrict__ out_idx_f) {
    __shared__ float xr[DD];
    __shared__ float s_rv[256];
    __shared__ int   s_ri[256];
    const int tid = threadIdx.x;
    const int nf = g_nflag;
    for (int f = blockIdx.x; f < nf; f += gridDim.x) {
        const int row = g_flag[f];
        if (g_tilebad[row >> 7]) continue;    // tile redone exactly already
        const float* xp = x + (size_t)row * DD;
        if (tid < DD) xr[tid] = xp[tid];
        __syncthreads();
        float bv = 3.4e38f; int bi = 0;
        #pragma unroll
        for (int r = 0; r < 4; ++r) {
            int k = tid + r * 256;
            const float* cp = cb + (size_t)k * DD;
            float dot = 0.f;
            #pragma unroll 8
            for (int d = 0; d < DD; ++d) dot = fmaf(xr[d], cp[d], dot);
            float v = g_csq[k] - 2.f * dot;
            if (v < bv) { bv = v; bi = k; }
        }
        s_rv[tid] = bv; s_ri[tid] = bi;
        __syncthreads();
        #pragma unroll
        for (int o = 128; o; o >>= 1) {
            if (tid < o) {
                float v = s_rv[tid + o]; int ix = s_ri[tid + o];
                if (v < s_rv[tid] || (v == s_rv[tid] && ix < s_ri[tid])) {
                    s_rv[tid] = v; s_ri[tid] = ix;
                }
            }
            __syncthreads();
        }
        if (tid == 0) {
            g_idx[row] = s_ri[0];
            out_idx_f[row] = (float)s_ri[0];
        }
        __syncthreads();
    }
}

// ---------------- epilogue kernels -----------------------------------------
__global__ void gather_loss_kernel(const float* __restrict__ x,
                                   const float* __restrict__ cb,
                                   float* __restrict__ out) {
    __shared__ float red[256];
    float local = 0.f;
    const int total = NN * (DD / 4);
    for (int i = blockIdx.x * 256 + threadIdx.x; i < total; i += gridDim.x * 256) {
        int row = i >> 6;
        int d4 = i & 63;
        int idx = g_idx[row];
        float4 q = ((const float4*)(cb + (size_t)idx * DD))[d4];
        float4 xv = ((const float4*)x)[i];
        ((float4*)out)[i] = q;
        float dx = xv.x - q.x, dy = xv.y - q.y, dz = xv.z - q.z, dw = xv.w - q.w;
        local += dx * dx + dy * dy + dz * dz + dw * dw;
    }
    red[threadIdx.x] = local;
    __syncthreads();
    #pragma unroll
    for (int o = 128; o; o >>= 1) {
        if (threadIdx.x < o) red[threadIdx.x] += red[threadIdx.x + o];
        __syncthreads();
    }
    if (threadIdx.x == 0) atomicAdd(&g_sse, red[0]);
}

__global__ void hist_kernel() {
    __shared__ float h[KK];
    for (int k = threadIdx.x; k < KK; k += 256) h[k] = 0.f;
    __syncthreads();
    for (int i = blockIdx.x * 256 + threadIdx.x; i < NN; i += gridDim.x * 256)
        atomicAdd(&h[g_idx[i]], 1.0f);
    __syncthreads();
    for (int k = threadIdx.x; k < KK; k += 256)
        if (h[k] != 0.f) atomicAdd(&g_counts[k], h[k]);
}

__global__ void finalize_kernel(float* __restrict__ out) {
    __shared__ float red[KK];
    int k = threadIdx.x;
    float p = g_counts[k] * (1.0f / (float)NN);
    red[k] = p * logf(p + 1e-10f);
    __syncthreads();
    #pragma unroll
    for (int o = 512; o; o >>= 1) {
        if (k < o) red[k] += red[k + o];
        __syncthreads();
    }
    if (k == 0) {
        out[(size_t)NN * DD]     = g_sse / (float)((size_t)NN * DD);
        out[(size_t)NN * DD + 1] = expf(-red[0]);
    }
}

// ---------------- launch ----------------------------------------------------
extern "C" void kernel_launch(void* const* d_in, const int* in_sizes, int n_in,
                              void* d_out, int out_size) {
    const float* x  = (const float*)d_in[0];
    const float* cb = (const float*)d_in[1];
    float* out = (float*)d_out;
    float* out_idx = out + (size_t)NN * DD + 2;

    cudaFuncSetAttribute(argmin_mma_kernel,
                         cudaFuncAttributeMaxDynamicSharedMemorySize, SM_TOTAL);

    init_kernel<<<4, 256>>>();
    convert_kernel<<<2048, 256>>>(x, g_xhi, g_xlo, NN * DD / 4);
    convert_kernel<<<64, 256>>>(cb, g_chi, g_clo, KK * DD / 4);
    csq_kernel<<<(KK * 32 + 255) / 256, 256>>>(cb);
    argmin_mma_kernel<<<NN / 128, 256, SM_TOTAL>>>(out_idx);
    validate_kernel<<<NN / 128, 256>>>(x, cb);
    argmin_exact_kernel<<<NN / 128, 256>>>(x, cb, out_idx);
    rescan_kernel<<<256, 256>>>(x, cb, out_idx);
    gather_loss_kernel<<<2048, 256>>>(x, cb, out);
    hist_kernel<<<64, 256>>>();
    finalize_kernel<<<1, KK>>>(out);
}

// round 10
// speedup vs baseline: 1.0831x; 1.0831x over previous
#include <cuda_runtime.h>
#include <cuda_fp16.h>
#include <math.h>
#include <stdint.h>

#define NN 65536
#define KK 1024
#define DD 256
#define MARGIN 1.5f
#define VTOL   2.0f

// ---------------- device scratch (static: no allocation allowed) ----------
__device__ __align__(256) __half g_xh[(size_t)NN * DD];
__device__ __align__(256) __half g_ch[(size_t)KK * DD];
__device__ float g_csq[KK];
__device__ int   g_idx[NN];
__device__ float g_bv[NN];
__device__ int   g_tilebad[NN / 128];
__device__ float g_counts[KK];
__device__ float g_sse;
__device__ int   g_nflag;
__device__ int   g_flag[NN];

// ---------------- helpers ---------------------------------------------------
__device__ __forceinline__ unsigned long long pk2(float lo, float hi) {
    unsigned long long r;
    asm("mov.b64 %0, {%1, %2};" : "=l"(r) : "f"(lo), "f"(hi));
    return r;
}
__device__ __forceinline__ void unpk2(unsigned long long v, float& lo, float& hi) {
    asm("mov.b64 {%0, %1}, %2;" : "=f"(lo), "=f"(hi) : "l"(v));
}
__device__ __forceinline__ void fma2(unsigned long long& acc,
                                     unsigned long long a, unsigned long long b) {
    asm("fma.rn.f32x2 %0, %1, %2, %0;" : "+l"(acc) : "l"(a), "l"(b));
}

// ---------------- setup kernels --------------------------------------------
__global__ void init_kernel() {
    int t = blockIdx.x * blockDim.x + threadIdx.x;
    if (t < KK) g_counts[t] = 0.f;
    if (t < NN / 128) g_tilebad[t] = 0;
    if (t == 0) { g_sse = 0.f; g_nflag = 0; }
}

__global__ void convert_h_kernel(const float* __restrict__ src,
                                 __half* __restrict__ dst, int ngroups) {
    __half2* d = (__half2*)dst;
    for (int i = blockIdx.x * blockDim.x + threadIdx.x; i < ngroups; i += gridDim.x * blockDim.x) {
        float4 v = ((const float4*)src)[i];
        d[i * 2]     = __floats2half2_rn(v.x, v.y);
        d[i * 2 + 1] = __floats2half2_rn(v.z, v.w);
    }
}

__global__ void csq_kernel(const float* __restrict__ cb) {
    int warp = (blockIdx.x * blockDim.x + threadIdx.x) >> 5;
    int lane = threadIdx.x & 31;
    if (warp >= KK) return;
    const float* c = cb + (size_t)warp * DD;
    float s = 0.f;
    #pragma unroll
    for (int d = lane; d < DD; d += 32) { float v = c[d]; s += v * v; }
    #pragma unroll
    for (int o = 16; o; o >>= 1) s += __shfl_down_sync(0xffffffffu, s, o);
    if (lane == 0) g_csq[warp] = s;
}

// ---------------- main fp16 HFMA2 argmin kernel -----------------------------
// Proven round-2 skeleton: 128 rows x 8 col-tiles of 128 x chunks of 32 elems.
// smem [depth(h2)][row]; 8x8 micro-tile; half2 accumulators (2 chains of 128).
__global__ void __launch_bounds__(256, 2) argmin_h2_kernel(float* __restrict__ out_idx_f) {
    __shared__ __half2 As2[16][136];
    __shared__ __half2 Bs2[16][136];
    __shared__ float s_csq[KK];
    __shared__ float s_v1[128 * 16];
    __shared__ float s_v2[128 * 16];
    __shared__ int   s_i1[128 * 16];

    const int tid = threadIdx.x;
    const int tx = tid & 15;           // col group: cols tx*8..+7
    const int ty = tid >> 4;           // row group: rows ty*8..+7
    const int row_base = blockIdx.x * 128;
    const int lr = tid >> 1;           // load row 0..127
    const int lq = (tid & 1) * 2;      // uint4 index base (0 or 2)

    #pragma unroll
    for (int i = 0; i < 4; ++i) s_csq[tid + i * 256] = g_csq[tid + i * 256];

    float tb1[8], tb2[8];
    int   ti1[8];
    #pragma unroll
    for (int i = 0; i < 8; ++i) { tb1[i] = 3.4e38f; tb2[i] = 3.4e38f; ti1[i] = 0; }

    for (int kt = 0; kt < 8; ++kt) {
        __half2 acc[8][8];
        #pragma unroll
        for (int i = 0; i < 8; ++i)
            #pragma unroll
            for (int j = 0; j < 8; ++j) acc[i][j] = __floats2half2_rn(0.f, 0.f);

        for (int dc = 0; dc < 8; ++dc) {
            const uint4* xa = (const uint4*)(g_xh + (size_t)(row_base + lr) * DD + dc * 32);
            const uint4* ca = (const uint4*)(g_ch + (size_t)(kt * 128 + lr) * DD + dc * 32);
            uint4 xv0 = xa[lq], xv1 = xa[lq + 1];
            uint4 cv0 = ca[lq], cv1 = ca[lq + 1];
            __syncthreads();   // previous chunk fully consumed
            #pragma unroll
            for (int t = 0; t < 4; ++t) {
                As2[lq * 4 + t][lr]     = ((__half2*)&xv0)[t];
                As2[lq * 4 + 4 + t][lr] = ((__half2*)&xv1)[t];
                Bs2[lq * 4 + t][lr]     = ((__half2*)&cv0)[t];
                Bs2[lq * 4 + 4 + t][lr] = ((__half2*)&cv1)[t];
            }
            __syncthreads();

            #pragma unroll
            for (int kk = 0; kk < 16; ++kk) {
                __half2 a[8], b[8];
                *(uint4*)&a[0] = *(const uint4*)&As2[kk][ty * 8];
                *(uint4*)&a[4] = *(const uint4*)&As2[kk][ty * 8 + 4];
                *(uint4*)&b[0] = *(const uint4*)&Bs2[kk][tx * 8];
                *(uint4*)&b[4] = *(const uint4*)&Bs2[kk][tx * 8 + 4];
                #pragma unroll
                for (int i = 0; i < 8; ++i)
                    #pragma unroll
                    for (int j = 0; j < 8; ++j)
                        acc[i][j] = __hfma2(a[i], b[j], acc[i][j]);
            }
        }

        // fold col-tile into per-thread top-2 (cols ascending per thread)
        #pragma unroll
        for (int j = 0; j < 8; ++j) {
            const int col = kt * 128 + tx * 8 + j;
            const float cq = s_csq[col];
            #pragma unroll
            for (int i = 0; i < 8; ++i) {
                float dot = __low2float(acc[i][j]) + __high2float(acc[i][j]);
                float v = fmaf(-2.f, dot, cq);
                if (v < tb1[i])      { tb2[i] = tb1[i]; tb1[i] = v; ti1[i] = col; }
                else if (v < tb2[i]) { tb2[i] = v; }
            }
        }
    }

    #pragma unroll
    for (int i = 0; i < 8; ++i) {
        const int slot = (ty * 8 + i) * 16 + tx;
        s_v1[slot] = tb1[i]; s_v2[slot] = tb2[i]; s_i1[slot] = ti1[i];
    }
    __syncthreads();
    if (tid < 128) {
        float b1 = 3.4e38f, b2 = 3.4e38f;
        int   i1 = 0;
        #pragma unroll
        for (int s = 0; s < 16; ++s) {
            float v1 = s_v1[tid * 16 + s];
            float v2 = s_v2[tid * 16 + s];
            int   ix = s_i1[tid * 16 + s];
            if (v1 < b1 || (v1 == b1 && ix < i1)) { b2 = fminf(b1, v2); b1 = v1; i1 = ix; }
            else { b2 = fminf(b2, v1); }
        }
        const int row = row_base + tid;
        g_idx[row] = i1;
        g_bv[row] = b1;
        out_idx_f[row] = (float)i1;
        if (b2 - b1 < MARGIN) {
            int s = atomicAdd(&g_nflag, 1);
            g_flag[s] = row;
        }
    }
}

// ---------------- validation: exact score of chosen index vs claimed -------
__global__ void validate_kernel(const float* __restrict__ x,
                                const float* __restrict__ cb) {
    const int r = threadIdx.x >> 1;
    const int h = threadIdx.x & 1;
    const int row = blockIdx.x * 128 + r;
    const int idx = g_idx[row];
    const float4* xp = (const float4*)(x + (size_t)row * DD) + h * 32;
    const float4* cp = (const float4*)(cb + (size_t)idx * DD) + h * 32;
    float dot = 0.f;
    #pragma unroll
    for (int i = 0; i < 32; ++i) {
        float4 a = xp[i], b = cp[i];
        dot += a.x * b.x + a.y * b.y + a.z * b.z + a.w * b.w;
    }
    dot += __shfl_xor_sync(0xffffffffu, dot, 1);
    if (h == 0) {
        float s = g_csq[idx] - 2.f * dot;
        if (fabsf(s - g_bv[row]) > VTOL) g_tilebad[blockIdx.x] = 1;
    }
}

// ---------------- exact fp32 fallback (tile-gated, proven) ------------------
__global__ void __launch_bounds__(256) argmin_exact_kernel(
    const float* __restrict__ x,
    const float* __restrict__ cb,
    float* __restrict__ out_idx_f)
{
    if (!g_tilebad[blockIdx.x]) return;
    __shared__ float As[8][132];
    __shared__ float Bs[8][132];
    __shared__ float s_val[128 * 16];
    __shared__ int   s_idx[128 * 16];

    const int tid = threadIdx.x;
    const int tx = tid & 15;
    const int ty = tid >> 4;
    const int row_base = blockIdx.x * 128;
    const int lr = tid >> 1;
    const int lc = (tid & 1) * 4;

    float best_val[8];
    int   best_idx[8];
    #pragma unroll
    for (int i = 0; i < 8; ++i) { best_val[i] = 3.4e38f; best_idx[i] = 0; }

    for (int kt = 0; kt < KK / 128; ++kt) {
        unsigned long long acc2[4][8];
        #pragma unroll
        for (int i = 0; i < 4; ++i)
            #pragma unroll
            for (int j = 0; j < 8; ++j) acc2[i][j] = 0ULL;

        for (int dc = 0; dc < DD / 8; ++dc) {
            const int d0 = dc * 8;
            float4 av = *(const float4*)(x  + (size_t)(row_base + lr)  * DD + d0 + lc);
            float4 bv = *(const float4*)(cb + (size_t)(kt * 128 + lr) * DD + d0 + lc);
            __syncthreads();
            As[lc + 0][lr] = av.x; As[lc + 1][lr] = av.y;
            As[lc + 2][lr] = av.z; As[lc + 3][lr] = av.w;
            Bs[lc + 0][lr] = bv.x; Bs[lc + 1][lr] = bv.y;
            Bs[lc + 2][lr] = bv.z; Bs[lc + 3][lr] = bv.w;
            __syncthreads();

            #pragma unroll
            for (int kk = 0; kk < 8; ++kk) {
                float4 a0 = *(const float4*)&As[kk][ty * 8];
                float4 a1 = *(const float4*)&As[kk][ty * 8 + 4];
                float4 b0 = *(const float4*)&Bs[kk][tx * 8];
                float4 b1 = *(const float4*)&Bs[kk][tx * 8 + 4];
                unsigned long long ap[4];
                ap[0] = pk2(a0.x, a0.y); ap[1] = pk2(a0.z, a0.w);
                ap[2] = pk2(a1.x, a1.y); ap[3] = pk2(a1.z, a1.w);
                float bf[8] = {b0.x, b0.y, b0.z, b0.w, b1.x, b1.y, b1.z, b1.w};
                #pragma unroll
                for (int j = 0; j < 8; ++j) {
                    unsigned long long bj = pk2(bf[j], bf[j]);
                    #pragma unroll
                    for (int i = 0; i < 4; ++i) fma2(acc2[i][j], ap[i], bj);
                }
            }
        }

        const int colb = kt * 128 + tx * 8;
        #pragma unroll
        for (int j = 0; j < 8; ++j) {
            const float cq = g_csq[colb + j];
            const int col = colb + j;
            #pragma unroll
            for (int i = 0; i < 4; ++i) {
                float lo, hi;
                unpk2(acc2[i][j], lo, hi);
                float v0 = cq - 2.f * lo;
                float v1 = cq - 2.f * hi;
                if (v0 < best_val[2 * i])     { best_val[2 * i]     = v0; best_idx[2 * i]     = col; }
                if (v1 < best_val[2 * i + 1]) { best_val[2 * i + 1] = v1; best_idx[2 * i + 1] = col; }
            }
        }
    }

    #pragma unroll
    for (int i = 0; i < 8; ++i) {
        s_val[(ty * 8 + i) * 16 + tx] = best_val[i];
        s_idx[(ty * 8 + i) * 16 + tx] = best_idx[i];
    }
    __syncthreads();
    if (tid < 128) {
        float bv = s_val[tid * 16];
        int   bi = s_idx[tid * 16];
        #pragma unroll
        for (int t = 1; t < 16; ++t) {
            float v  = s_val[tid * 16 + t];
            int   ix = s_idx[tid * 16 + t];
            if (v < bv || (v == bv && ix < bi)) { bv = v; bi = ix; }
        }
        g_idx[row_base + tid] = bi;
        out_idx_f[row_base + tid] = (float)bi;
    }
}

// ---------------- tiled exact rescan over flagged rows ----------------------
__global__ void __launch_bounds__(256) rescan_gemm_kernel(
    const float* __restrict__ x,
    const float* __restrict__ cb,
    float* __restrict__ out_idx_f)
{
    const int nf = g_nflag;
    if (blockIdx.x * 128 >= nf) return;
    __shared__ int   rows_s[128];
    __shared__ float As[8][132];
    __shared__ float Bs[8][132];
    __shared__ float s_val[128 * 16];
    __shared__ int   s_idx[128 * 16];

    const int tid = threadIdx.x;
    const int tx = tid & 15;
    const int ty = tid >> 4;
    const int lr = tid >> 1;
    const int lc = (tid & 1) * 4;

    if (tid < 128) {
        int f = blockIdx.x * 128 + tid;
        rows_s[tid] = g_flag[f < nf ? f : nf - 1];
    }
    __syncthreads();

    float best_val[8];
    int   best_idx[8];
    #pragma unroll
    for (int i = 0; i < 8; ++i) { best_val[i] = 3.4e38f; best_idx[i] = 0; }

    const int myrow = rows_s[lr];
    for (int kt = 0; kt < KK / 128; ++kt) {
        unsigned long long acc2[4][8];
        #pragma unroll
        for (int i = 0; i < 4; ++i)
            #pragma unroll
            for (int j = 0; j < 8; ++j) acc2[i][j] = 0ULL;

        for (int dc = 0; dc < DD / 8; ++dc) {
            const int d0 = dc * 8;
            float4 av = *(const float4*)(x  + (size_t)myrow * DD + d0 + lc);
            float4 bv = *(const float4*)(cb + (size_t)(kt * 128 + lr) * DD + d0 + lc);
            __syncthreads();
            As[lc + 0][lr] = av.x; As[lc + 1][lr] = av.y;
            As[lc + 2][lr] = av.z; As[lc + 3][lr] = av.w;
            Bs[lc + 0][lr] = bv.x; Bs[lc + 1][lr] = bv.y;
            Bs[lc + 2][lr] = bv.z; Bs[lc + 3][lr] = bv.w;
            __syncthreads();

            #pragma unroll
            for (int kk = 0; kk < 8; ++kk) {
                float4 a0 = *(const float4*)&As[kk][ty * 8];
                float4 a1 = *(const float4*)&As[kk][ty * 8 + 4];
                float4 b0 = *(const float4*)&Bs[kk][tx * 8];
                float4 b1 = *(const float4*)&Bs[kk][tx * 8 + 4];
                unsigned long long ap[4];
                ap[0] = pk2(a0.x, a0.y); ap[1] = pk2(a0.z, a0.w);
                ap[2] = pk2(a1.x, a1.y); ap[3] = pk2(a1.z, a1.w);
                float bf[8] = {b0.x, b0.y, b0.z, b0.w, b1.x, b1.y, b1.z, b1.w};
                #pragma unroll
                for (int j = 0; j < 8; ++j) {
                    unsigned long long bj = pk2(bf[j], bf[j]);
                    #pragma unroll
                    for (int i = 0; i < 4; ++i) fma2(acc2[i][j], ap[i], bj);
                }
            }
        }

        const int colb = kt * 128 + tx * 8;
        #pragma unroll
        for (int j = 0; j < 8; ++j) {
            const float cq = g_csq[colb + j];
            const int col = colb + j;
            #pragma unroll
            for (int i = 0; i < 4; ++i) {
                float lo, hi;
                unpk2(acc2[i][j], lo, hi);
                float v0 = cq - 2.f * lo;
                float v1 = cq - 2.f * hi;
                if (v0 < best_val[2 * i])     { best_val[2 * i]     = v0; best_idx[2 * i]     = col; }
                if (v1 < best_val[2 * i + 1]) { best_val[2 * i + 1] = v1; best_idx[2 * i + 1] = col; }
            }
        }
    }

    #pragma unroll
    for (int i = 0; i < 8; ++i) {
        s_val[(ty * 8 + i) * 16 + tx] = best_val[i];
        s_idx[(ty * 8 + i) * 16 + tx] = best_idx[i];
    }
    __syncthreads();
    if (tid < 128 && blockIdx.x * 128 + tid < nf) {
        float bv = s_val[tid * 16];
        int   bi = s_idx[tid * 16];
        #pragma unroll
        for (int t = 1; t < 16; ++t) {
            float v  = s_val[tid * 16 + t];
            int   ix = s_idx[tid * 16 + t];
            if (v < bv || (v == bv && ix < bi)) { bv = v; bi = ix; }
        }
        const int row = rows_s[tid];
        g_idx[row] = bi;
        out_idx_f[row] = (float)bi;
    }
}

// ---------------- epilogue kernels -----------------------------------------
__global__ void gather_loss_kernel(const float* __restrict__ x,
                                   const float* __restrict__ cb,
                                   float* __restrict__ out) {
    __shared__ float red[256];
    float local = 0.f;
    const int total = NN * (DD / 4);
    for (int i = blockIdx.x * 256 + threadIdx.x; i < total; i += gridDim.x * 256) {
        int row = i >> 6;
        int d4 = i & 63;
        int idx = g_idx[row];
        float4 q = ((const float4*)(cb + (size_t)idx * DD))[d4];
        float4 xv = ((const float4*)x)[i];
        ((float4*)out)[i] = q;
        float dx = xv.x - q.x, dy = xv.y - q.y, dz = xv.z - q.z, dw = xv.w - q.w;
        local += dx * dx + dy * dy + dz * dz + dw * dw;
    }
    red[threadIdx.x] = local;
    __syncthreads();
    #pragma unroll
    for (int o = 128; o; o >>= 1) {
        if (threadIdx.x < o) red[threadIdx.x] += red[threadIdx.x + o];
        __syncthreads();
    }
    if (threadIdx.x == 0) atomicAdd(&g_sse, red[0]);
}

__global__ void hist_kernel() {
    __shared__ float h[KK];
    for (int k = threadIdx.x; k < KK; k += 256) h[k] = 0.f;
    __syncthreads();
    for (int i = blockIdx.x * 256 + threadIdx.x; i < NN; i += gridDim.x * 256)
        atomicAdd(&h[g_idx[i]], 1.0f);
    __syncthreads();
    for (int k = threadIdx.x; k < KK; k += 256)
        if (h[k] != 0.f) atomicAdd(&g_counts[k], h[k]);
}

__global__ void finalize_kernel(float* __restrict__ out) {
    __shared__ float red[KK];
    int k = threadIdx.x;
    float p = g_counts[k] * (1.0f / (float)NN);
    red[k] = p * logf(p + 1e-10f);
    __syncthreads();
    #pragma unroll
    for (int o = 512; o; o >>= 1) {
        if (k < o) red[k] += red[k + o];
        __syncthreads();
    }
    if (k == 0) {
        out[(size_t)NN * DD]     = g_sse / (float)((size_t)NN * DD);
        out[(size_t)NN * DD + 1] = expf(-red[0]);
    }
}

// ---------------- launch ----------------------------------------------------
extern "C" void kernel_launch(void* const* d_in, const int* in_sizes, int n_in,
                              void* d_out, int out_size) {
    const float* x  = (const float*)d_in[0];
    const float* cb = (const float*)d_in[1];
    float* out = (float*)d_out;
    float* out_idx = out + (size_t)NN * DD + 2;

    init_kernel<<<4, 256>>>();
    convert_h_kernel<<<2048, 256>>>(x, g_xh, NN * DD / 4);
    convert_h_kernel<<<64, 256>>>(cb, g_ch, KK * DD / 4);
    csq_kernel<<<(KK * 32 + 255) / 256, 256>>>(cb);
    argmin_h2_kernel<<<NN / 128, 256>>>(out_idx);
    validate_kernel<<<NN / 128, 256>>>(x, cb);
    argmin_exact_kernel<<<NN / 128, 256>>>(x, cb, out_idx);
    rescan_gemm_kernel<<<NN / 128, 256>>>(x, cb, out_idx);
    gather_loss_kernel<<<2048, 256>>>(x, cb, out);
    hist_kernel<<<64, 256>>>();
    finalize_kernel<<<1, KK>>>(out);
}